// round 6
// baseline (speedup 1.0000x reference)
#include <cuda_runtime.h>
#include <math.h>

#define BATCH 4
#define CIN   64
#define COUT  64
#define HH    192
#define WW    192
#define NTAP  9
#define KTOT  576          // CIN * NTAP
#define HW    (HH*WW)

// ---------------- scratch (device globals; no allocations allowed) ----------
__device__ float g_off [BATCH*18*HW];     // offset conv output (y: ch 0..8, x: ch 9..17)
__device__ float g_mask[BATCH*NTAP*HW];   // sigmoid(mask conv)
__device__ float g_conv[BATCH*COUT*HW];   // pre-BN main conv output
__device__ float g_sum  [COUT];
__device__ float g_sqsum[COUT];

// ---------------- K0: zero the BN stats -------------------------------------
__global__ void k0_zero() {
    int t = threadIdx.x;
    if (t < COUT) { g_sum[t] = 0.f; g_sqsum[t] = 0.f; }
}

// ---------------- K1: fused offset(18ch) + mask(9ch) 3x3 conv ---------------
// Block: one image row (b, h). 192 threads = 4 oc-groups x 48 pixel-threads,
// each pixel-thread owns 4 consecutive pixels (full 192-wide row).
// Per input channel: stage 3x194 input rows + 27x9 weights in smem, then
// 7 oc x 9 taps x 4 px FMAs per thread (weights amortized over 4 pixels).
__global__ __launch_bounds__(192) void k1_offmask(
    const float* __restrict__ x,
    const float* __restrict__ w_p, const float* __restrict__ b_p,
    const float* __restrict__ w_m, const float* __restrict__ b_m)
{
    __shared__ float xrow[3*194];
    __shared__ float wsm[252];           // 28 oc slots (27 real + 1 pad) x 9
    const int h = blockIdx.x, b = blockIdx.y;
    const int t = threadIdx.x;
    const int g = t / 48, pt = t % 48;   // oc-group, pixel group (4 px each)

    float acc[7][4];
#pragma unroll
    for (int j = 0; j < 7; j++)
#pragma unroll
        for (int p = 0; p < 4; p++) acc[j][p] = 0.f;

    for (int c = 0; c < CIN; c++) {
        // stage input rows h-1..h+1, cols -1..192 (zero padded)
        for (int i = t; i < 582; i += 192) {
            int r = i / 194, cc = i % 194;
            int gr = h - 1 + r, gc = cc - 1;
            float v = 0.f;
            if (gr >= 0 && gr < HH && gc >= 0 && gc < WW)
                v = x[((b*CIN + c)*HH + gr)*WW + gc];
            xrow[i] = v;
        }
        // stage 27 filters for this channel (18 offset + 9 mask), pad to 28
        for (int i = t; i < 252; i += 192) {
            float v = 0.f;
            if (i < 243) {
                int oc = i / 9, k = i % 9;
                v = (oc < 18) ? w_p[(oc*CIN + c)*9 + k]
                              : w_m[((oc-18)*CIN + c)*9 + k];
            }
            wsm[i] = v;
        }
        __syncthreads();

        float v[3][6];
#pragma unroll
        for (int r = 0; r < 3; r++)
#pragma unroll
            for (int j = 0; j < 6; j++)
                v[r][j] = xrow[r*194 + pt*4 + j];

#pragma unroll
        for (int j = 0; j < 7; j++) {
            int ocl = g*7 + j;           // up to 27 (pad slot, weights = 0)
#pragma unroll
            for (int ky = 0; ky < 3; ky++)
#pragma unroll
                for (int kx = 0; kx < 3; kx++) {
                    float wv = wsm[ocl*9 + ky*3 + kx];
#pragma unroll
                    for (int p = 0; p < 4; p++)
                        acc[j][p] = fmaf(wv, v[ky][p+kx], acc[j][p]);
                }
        }
        __syncthreads();
    }

    const int w0 = pt*4;
#pragma unroll
    for (int j = 0; j < 7; j++) {
        int oc = g*7 + j;
        if (oc < 18) {
            float bb = b_p[oc];
            float4 o4 = make_float4(acc[j][0]+bb, acc[j][1]+bb,
                                    acc[j][2]+bb, acc[j][3]+bb);
            *(float4*)&g_off[((b*18 + oc)*HH + h)*WW + w0] = o4;
        } else if (oc < 27) {
            int mc = oc - 18;
            float bb = b_m[mc];
            float4 o4;
            o4.x = 1.f/(1.f+expf(-(acc[j][0]+bb)));
            o4.y = 1.f/(1.f+expf(-(acc[j][1]+bb)));
            o4.z = 1.f/(1.f+expf(-(acc[j][2]+bb)));
            o4.w = 1.f/(1.f+expf(-(acc[j][3]+bb)));
            *(float4*)&g_mask[((b*NTAP + mc)*HH + h)*WW + w0] = o4;
        }
    }
}

// ---------------- K2: deformable sample + main conv + BN partial stats ------
// Block: 32-pixel row segment (b, h, w0..w0+31). 128 threads.
// Phase A1: per (pixel,tap) build 4 gather indices + 4 weights (g * mask; OOB->0)
// Phase A2: sample xs[k=c*9+n][p] into smem (4 gathers each, near-coalesced)
// Phase B : k-chunked GEMM out[o][p] += w[o][k]*xs[k][p], 4o x 4p per thread.
__global__ __launch_bounds__(128) void k2_main(
    const float* __restrict__ x,
    const float* __restrict__ wconv)
{
    extern __shared__ float smem[];
    float*  xs   = smem;                          // 18432 floats
    int4*   id4  = (int4*) (smem + 18432);        // 288 int4  (1152 words)
    float4* wg4  = (float4*)(smem + 18432 + 1152);// 288 float4 (1152 words)
    float*  w_s  = smem + 18432 + 2304;           // 64*68 = 4352 words
    float*  ssum = w_s + 4352;                    // 64
    float*  ssq  = ssum + 64;                     // 64

    const int w0 = blockIdx.x * 32, h = blockIdx.y, b = blockIdx.z;
    const int t = threadIdx.x;

    if (t < 64) { ssum[t] = 0.f; ssq[t] = 0.f; }

    // ---- Phase A1: gather tables for 32 px x 9 taps
    for (int it = t; it < 288; it += 128) {
        int p = it / 9, n = it % 9;
        int wpix = w0 + p;
        float offy = g_off [((b*18   + n    )*HH + h)*WW + wpix];
        float offx = g_off [((b*18   + 9 + n)*HH + h)*WW + wpix];
        float m    = g_mask[((b*NTAP + n    )*HH + h)*WW + wpix];

        float py = (float)(h + 1)    + (float)(n/3 - 1) + offy;  // padded coords
        float px = (float)(wpix + 1) + (float)(n%3 - 1) + offx;
        float fy = floorf(py), fx = floorf(px);
        float qy0 = fminf(fmaxf(fy,       0.f), 193.f);
        float qy1 = fminf(fmaxf(fy + 1.f, 0.f), 193.f);
        float qx0 = fminf(fmaxf(fx,       0.f), 193.f);
        float qx1 = fminf(fmaxf(fx + 1.f, 0.f), 193.f);
        float pyc = fminf(fmaxf(py, 0.f), 193.f);
        float pxc = fminf(fmaxf(px, 0.f), 193.f);
        float gy0 = 1.f + (qy0 - pyc);
        float gy1 = 1.f - (qy1 - pyc);
        float gx0 = 1.f + (qx0 - pxc);
        float gx1 = 1.f - (qx1 - pxc);
        int iy0 = (int)qy0, iy1 = (int)qy1, ix0 = (int)qx0, ix1 = (int)qx1;

        int4 id; float4 wg;
        // lt (y0,x0)
        bool inb = (iy0 >= 1) & (iy0 <= 192) & (ix0 >= 1) & (ix0 <= 192);
        id.x = inb ? (iy0-1)*WW + (ix0-1) : 0;  wg.x = inb ? gy0*gx0*m : 0.f;
        // rb (y1,x1)
        inb = (iy1 >= 1) & (iy1 <= 192) & (ix1 >= 1) & (ix1 <= 192);
        id.y = inb ? (iy1-1)*WW + (ix1-1) : 0;  wg.y = inb ? gy1*gx1*m : 0.f;
        // lb (y0,x1)
        inb = (iy0 >= 1) & (iy0 <= 192) & (ix1 >= 1) & (ix1 <= 192);
        id.z = inb ? (iy0-1)*WW + (ix1-1) : 0;  wg.z = inb ? gy0*gx1*m : 0.f;
        // rt (y1,x0)
        inb = (iy1 >= 1) & (iy1 <= 192) & (ix0 >= 1) & (ix0 <= 192);
        id.w = inb ? (iy1-1)*WW + (ix0-1) : 0;  wg.w = inb ? gy1*gx0*m : 0.f;

        id4[it] = id; wg4[it] = wg;
    }
    __syncthreads();

    // ---- Phase A2: sample into xs[k][p]
    for (int e = t; e < KTOT*32; e += 128) {
        int p = e & 31;
        int k = e >> 5;
        int c = k / 9, n = k - c*9;
        int it = p*9 + n;
        int4 id = id4[it];
        float4 wg = wg4[it];
        const float* base = x + (size_t)(b*CIN + c)*HW;
        float v = wg.x*base[id.x] + wg.y*base[id.y]
                + wg.z*base[id.z] + wg.w*base[id.w];
        xs[k*32 + p] = v;
    }
    __syncthreads();

    // ---- Phase B: GEMM (64 o) x (32 px) over 576 k, chunked by 64
    const int og = t & 15, pg = t >> 4;     // 16 o-groups x 8 px-groups
    float acc[4][4];
#pragma unroll
    for (int i = 0; i < 4; i++)
#pragma unroll
        for (int j = 0; j < 4; j++) acc[i][j] = 0.f;

    for (int kb = 0; kb < 9; kb++) {
        for (int i = t; i < 4096; i += 128) {
            int o = i >> 6, k = i & 63;
            w_s[k*68 + o] = wconv[o*KTOT + kb*64 + k];
        }
        __syncthreads();
#pragma unroll 8
        for (int k = 0; k < 64; k++) {
            float4 wv = *(const float4*)&w_s[k*68 + og*4];
            float4 xv = *(const float4*)&xs[(kb*64 + k)*32 + pg*4];
            acc[0][0] = fmaf(wv.x, xv.x, acc[0][0]);
            acc[0][1] = fmaf(wv.x, xv.y, acc[0][1]);
            acc[0][2] = fmaf(wv.x, xv.z, acc[0][2]);
            acc[0][3] = fmaf(wv.x, xv.w, acc[0][3]);
            acc[1][0] = fmaf(wv.y, xv.x, acc[1][0]);
            acc[1][1] = fmaf(wv.y, xv.y, acc[1][1]);
            acc[1][2] = fmaf(wv.y, xv.z, acc[1][2]);
            acc[1][3] = fmaf(wv.y, xv.w, acc[1][3]);
            acc[2][0] = fmaf(wv.z, xv.x, acc[2][0]);
            acc[2][1] = fmaf(wv.z, xv.y, acc[2][1]);
            acc[2][2] = fmaf(wv.z, xv.z, acc[2][2]);
            acc[2][3] = fmaf(wv.z, xv.w, acc[2][3]);
            acc[3][0] = fmaf(wv.w, xv.x, acc[3][0]);
            acc[3][1] = fmaf(wv.w, xv.y, acc[3][1]);
            acc[3][2] = fmaf(wv.w, xv.z, acc[3][2]);
            acc[3][3] = fmaf(wv.w, xv.w, acc[3][3]);
        }
        __syncthreads();
    }

    // ---- store conv output + per-channel partial stats
#pragma unroll
    for (int oo = 0; oo < 4; oo++) {
        int o = og*4 + oo;
        float4 r = make_float4(acc[oo][0], acc[oo][1], acc[oo][2], acc[oo][3]);
        *(float4*)&g_conv[((b*COUT + o)*HH + h)*WW + w0 + pg*4] = r;
        float s  = r.x + r.y + r.z + r.w;
        float sq = r.x*r.x + r.y*r.y + r.z*r.z + r.w*r.w;
        atomicAdd(&ssum[o], s);
        atomicAdd(&ssq[o], sq);
    }
    __syncthreads();
    if (t < 64) {
        atomicAdd(&g_sum[t],   ssum[t]);
        atomicAdd(&g_sqsum[t], ssq[t]);
    }
}

// ---------------- K4: BatchNorm (batch stats) + ReLU + MaxPool2 -------------
__global__ void k4_bnpool(const float* __restrict__ gamma,
                          const float* __restrict__ beta,
                          float* __restrict__ out)
{
    int idx = blockIdx.x * blockDim.x + threadIdx.x;
    const int TOT = BATCH*COUT*96*96;
    if (idx >= TOT) return;
    int wo = idx % 96;
    int ho = (idx / 96) % 96;
    int o  = (idx / (96*96)) % COUT;
    int b  = idx / (96*96*COUT);

    const float inv = 1.f / (float)(BATCH*HH*WW);
    float mean = g_sum[o] * inv;
    float var  = g_sqsum[o] * inv - mean*mean;
    float sc = gamma[o] * rsqrtf(var + 1e-5f);
    float sh = beta[o] - mean * sc;

    const float* src = g_conv + ((size_t)(b*COUT + o)*HH + 2*ho)*WW + 2*wo;
    float a0 = fmaf(sc, src[0],    sh);
    float a1 = fmaf(sc, src[1],    sh);
    float a2 = fmaf(sc, src[WW],   sh);
    float a3 = fmaf(sc, src[WW+1], sh);
    float m = fmaxf(fmaxf(a0, a1), fmaxf(a2, a3));
    out[idx] = fmaxf(m, 0.f);
}

// ---------------- launch -----------------------------------------------------
extern "C" void kernel_launch(void* const* d_in, const int* in_sizes, int n_in,
                              void* d_out, int out_size)
{
    const float* x     = (const float*)d_in[0];
    const float* w_p   = (const float*)d_in[1];
    const float* b_p   = (const float*)d_in[2];
    const float* w_m   = (const float*)d_in[3];
    const float* b_m   = (const float*)d_in[4];
    const float* wconv = (const float*)d_in[5];
    const float* gamma = (const float*)d_in[6];
    const float* beta  = (const float*)d_in[7];
    float* out = (float*)d_out;

    // 100864 B dynamic smem for k2 (> default 48KB). Sticky attribute; the
    // first (uncaptured correctness) call sets it, later calls are no-ops.
    cudaFuncSetAttribute(k2_main, cudaFuncAttributeMaxDynamicSharedMemorySize, 101376);

    k0_zero<<<1, 64>>>();
    k1_offmask<<<dim3(HH, BATCH), 192>>>(x, w_p, b_p, w_m, b_m);
    k2_main<<<dim3(WW/32, HH, BATCH), 128, 100864>>>(x, wconv);
    int tot = BATCH*COUT*96*96;
    k4_bnpool<<<(tot + 255)/256, 256>>>(gamma, beta, out);
}

// round 11
// speedup vs baseline: 1.3630x; 1.3630x over previous
#include <cuda_runtime.h>
#include <math.h>
#include <stdint.h>

#define BATCH 4
#define CIN   64
#define COUT  64
#define HH    192
#define WW    192
#define NTAP  9
#define KTOT  576          // CIN * NTAP
#define HW    (HH*WW)
#define PXT   128          // pixels per k2 block
#define KC    32           // K-chunk
#define NCHUNK (KTOT/KC)   // 18

// smem word layout for k2
#define AS_STRIDE 132      // As[32][132] k-major
#define BS_STRIDE 36       // Bs[64][36]  oc-major
#define CT_STRIDE 130      // Ct[64][130] epilogue transpose (reuses table area)
#define AS_WORDS  (KC*AS_STRIDE)            // 4224
#define BS_WORDS  (COUT*BS_STRIDE)          // 2304
#define TB_WORDS  (PXT*NTAP*8)              // 9216 (id4 + wg4)
#define K2_SMEM_BYTES ((AS_WORDS + BS_WORDS + TB_WORDS) * 4)   // 62976

// ---------------- scratch (device globals; no allocations allowed) ----------
__device__ float g_off [BATCH*18*HW];
__device__ float g_mask[BATCH*NTAP*HW];
__device__ float g_conv[BATCH*COUT*HW];
__device__ float g_sum  [COUT];
__device__ float g_sqsum[COUT];

__device__ __forceinline__ uint32_t f2tf32(float v) {
    uint32_t u;
    asm("cvt.rna.tf32.f32 %0, %1;" : "=r"(u) : "f"(v));
    return u;
}

__device__ __forceinline__ void mma_tf32(float* d, uint32_t a0, uint32_t a1,
                                         uint32_t a2, uint32_t a3,
                                         uint32_t b0, uint32_t b1) {
    asm volatile(
        "mma.sync.aligned.m16n8k8.row.col.f32.tf32.tf32.f32 "
        "{%0,%1,%2,%3}, {%4,%5,%6,%7}, {%8,%9}, {%0,%1,%2,%3};"
        : "+f"(d[0]), "+f"(d[1]), "+f"(d[2]), "+f"(d[3])
        : "r"(a0), "r"(a1), "r"(a2), "r"(a3), "r"(b0), "r"(b1));
}

// ---------------- K0: zero the BN stats -------------------------------------
__global__ void k0_zero() {
    int t = threadIdx.x;
    if (t < COUT) { g_sum[t] = 0.f; g_sqsum[t] = 0.f; }
}

// ---------------- K1: fused offset(18ch) + mask(9ch) 3x3 conv (unchanged) ---
__global__ __launch_bounds__(192) void k1_offmask(
    const float* __restrict__ x,
    const float* __restrict__ w_p, const float* __restrict__ b_p,
    const float* __restrict__ w_m, const float* __restrict__ b_m)
{
    __shared__ float xrow[3*194];
    __shared__ float wsm[252];
    const int h = blockIdx.x, b = blockIdx.y;
    const int t = threadIdx.x;
    const int g = t / 48, pt = t % 48;

    float acc[7][4];
#pragma unroll
    for (int j = 0; j < 7; j++)
#pragma unroll
        for (int p = 0; p < 4; p++) acc[j][p] = 0.f;

    for (int c = 0; c < CIN; c++) {
        for (int i = t; i < 582; i += 192) {
            int r = i / 194, cc = i % 194;
            int gr = h - 1 + r, gc = cc - 1;
            float v = 0.f;
            if (gr >= 0 && gr < HH && gc >= 0 && gc < WW)
                v = x[((b*CIN + c)*HH + gr)*WW + gc];
            xrow[i] = v;
        }
        for (int i = t; i < 252; i += 192) {
            float v = 0.f;
            if (i < 243) {
                int oc = i / 9, k = i % 9;
                v = (oc < 18) ? w_p[(oc*CIN + c)*9 + k]
                              : w_m[((oc-18)*CIN + c)*9 + k];
            }
            wsm[i] = v;
        }
        __syncthreads();

        float v[3][6];
#pragma unroll
        for (int r = 0; r < 3; r++)
#pragma unroll
            for (int j = 0; j < 6; j++)
                v[r][j] = xrow[r*194 + pt*4 + j];

#pragma unroll
        for (int j = 0; j < 7; j++) {
            int ocl = g*7 + j;
#pragma unroll
            for (int ky = 0; ky < 3; ky++)
#pragma unroll
                for (int kx = 0; kx < 3; kx++) {
                    float wv = wsm[ocl*9 + ky*3 + kx];
#pragma unroll
                    for (int p = 0; p < 4; p++)
                        acc[j][p] = fmaf(wv, v[ky][p+kx], acc[j][p]);
                }
        }
        __syncthreads();
    }

    const int w0 = pt*4;
#pragma unroll
    for (int j = 0; j < 7; j++) {
        int oc = g*7 + j;
        if (oc < 18) {
            float bb = b_p[oc];
            float4 o4 = make_float4(acc[j][0]+bb, acc[j][1]+bb,
                                    acc[j][2]+bb, acc[j][3]+bb);
            *(float4*)&g_off[((b*18 + oc)*HH + h)*WW + w0] = o4;
        } else if (oc < 27) {
            int mc = oc - 18;
            float bb = b_m[mc];
            float4 o4;
            o4.x = 1.f/(1.f+expf(-(acc[j][0]+bb)));
            o4.y = 1.f/(1.f+expf(-(acc[j][1]+bb)));
            o4.z = 1.f/(1.f+expf(-(acc[j][2]+bb)));
            o4.w = 1.f/(1.f+expf(-(acc[j][3]+bb)));
            *(float4*)&g_mask[((b*NTAP + mc)*HH + h)*WW + w0] = o4;
        }
    }
}

// ---------------- K2: deformable sample + mma.sync TF32 GEMM ----------------
// Block = 128 flat pixels of image b, 256 threads (8 warps).
// Warp w owns px rows [16w, 16w+16), all 64 oc. Accums in registers.
// Per K-chunk (32): stage A (k-major, swizzle-free padded) + B (oc-major),
// then 4 k-steps x 8 n-tiles of mma.m16n8k8.tf32.
__global__ __launch_bounds__(256) void k2_main(
    const float* __restrict__ x, const float* __restrict__ wconv)
{
    extern __shared__ float smem[];
    float*    As  = smem;                       // [32][132]
    float*    Bs  = smem + AS_WORDS;            // [64][36]
    float*    Tb  = smem + AS_WORDS + BS_WORDS; // tables, later Ct
    int4*     id4 = (int4*)Tb;                  // 1152 int4
    float4*   wg4 = (float4*)(Tb + 4608);       // 1152 float4
    uint32_t* Asu = (uint32_t*)As;
    uint32_t* Bsu = (uint32_t*)Bs;

    const int t = threadIdx.x;
    const int wid = t >> 5, lane = t & 31;
    const int fg = lane >> 2, fi = lane & 3;    // fragment group / id
    const int P0 = blockIdx.x * PXT;
    const int b  = blockIdx.y;

    // ---- gather tables: 128 px x 9 taps, stored [n][px]
    for (int it = t; it < PXT*NTAP; it += 256) {
        int n = it >> 7, px = it & 127;
        int P = P0 + px;
        int h = P / WW, w = P - h*WW;

        float offy = g_off [((b*18   + n    )*HH + h)*WW + w];
        float offx = g_off [((b*18   + 9 + n)*HH + h)*WW + w];
        float m    = g_mask[((b*NTAP + n    )*HH + h)*WW + w];

        float py  = (float)(h + 1) + (float)(n/3 - 1) + offy;   // padded coords
        float px_ = (float)(w + 1) + (float)(n%3 - 1) + offx;
        float fy = floorf(py), fx = floorf(px_);
        float qy0 = fminf(fmaxf(fy,       0.f), 193.f);
        float qy1 = fminf(fmaxf(fy + 1.f, 0.f), 193.f);
        float qx0 = fminf(fmaxf(fx,       0.f), 193.f);
        float qx1 = fminf(fmaxf(fx + 1.f, 0.f), 193.f);
        float pyc = fminf(fmaxf(py,  0.f), 193.f);
        float pxc = fminf(fmaxf(px_, 0.f), 193.f);
        float gy0 = 1.f + (qy0 - pyc);
        float gy1 = 1.f - (qy1 - pyc);
        float gx0 = 1.f + (qx0 - pxc);
        float gx1 = 1.f - (qx1 - pxc);
        int iy0 = (int)qy0, iy1 = (int)qy1, ix0 = (int)qx0, ix1 = (int)qx1;

        int4 id; float4 wg;
        bool inb = (iy0 >= 1) & (iy0 <= 192) & (ix0 >= 1) & (ix0 <= 192);
        id.x = inb ? (iy0-1)*WW + (ix0-1) : 0;  wg.x = inb ? gy0*gx0*m : 0.f;
        inb = (iy1 >= 1) & (iy1 <= 192) & (ix1 >= 1) & (ix1 <= 192);
        id.y = inb ? (iy1-1)*WW + (ix1-1) : 0;  wg.y = inb ? gy1*gx1*m : 0.f;
        inb = (iy0 >= 1) & (iy0 <= 192) & (ix1 >= 1) & (ix1 <= 192);
        id.z = inb ? (iy0-1)*WW + (ix1-1) : 0;  wg.z = inb ? gy0*gx1*m : 0.f;
        inb = (iy1 >= 1) & (iy1 <= 192) & (ix0 >= 1) & (ix0 <= 192);
        id.w = inb ? (iy1-1)*WW + (ix0-1) : 0;  wg.w = inb ? gy1*gx0*m : 0.f;

        id4[it] = id; wg4[it] = wg;
    }
    __syncthreads();

    float acc[8][4];
#pragma unroll
    for (int j = 0; j < 8; j++)
#pragma unroll
        for (int r = 0; r < 4; r++) acc[j][r] = 0.f;

    for (int chunk = 0; chunk < NCHUNK; ++chunk) {
        const int k0 = chunk * KC;

        // stage B: 64 oc x 32 k (coalesced gmem reads; Bs[oc][kl])
#pragma unroll
        for (int i = 0; i < 8; i++) {
            int e = t + i*256;
            int o = e >> 5, kl = e & 31;
            Bsu[o*BS_STRIDE + kl] = f2tf32(wconv[o*KTOT + k0 + kl]);
        }
        // sample A: 128 px x 32 k, stored k-major As[kl][px]
#pragma unroll
        for (int i = 0; i < 16; i++) {
            int e = t + i*256;
            int px = e & 127, kl = e >> 7;
            int k = k0 + kl;
            int c = k / 9, n = k - c*9;
            int4   id = id4[n*128 + px];
            float4 wg = wg4[n*128 + px];
            const float* base = x + (size_t)(b*CIN + c)*HW;
            float v = wg.x*base[id.x] + wg.y*base[id.y]
                    + wg.z*base[id.z] + wg.w*base[id.w];
            Asu[kl*AS_STRIDE + px] = f2tf32(v);
        }
        __syncthreads();

        const int px0 = wid * 16;
#pragma unroll
        for (int s = 0; s < 4; s++) {
            const uint32_t* Ab = Asu + (s*8 + fi)*AS_STRIDE + px0 + fg;
            uint32_t a0 = Ab[0];
            uint32_t a1 = Ab[8];
            uint32_t a2 = Ab[4*AS_STRIDE];
            uint32_t a3 = Ab[4*AS_STRIDE + 8];
#pragma unroll
            for (int j = 0; j < 8; j++) {
                const uint32_t* Bb = Bsu + (j*8 + fg)*BS_STRIDE + s*8 + fi;
                mma_tf32(acc[j], a0, a1, a2, a3, Bb[0], Bb[4]);
            }
        }
        __syncthreads();
    }

    // ---- epilogue: transpose through smem (reuse table area) for coalesced
    // stores. Ct[oc][px], stride 130 (bank-conflict-free for frag pattern).
    float* Ct = Tb;
    {
        const int px_r = wid*16 + fg;
        const int oc0  = fi*2;
#pragma unroll
        for (int j = 0; j < 8; j++) {
            int oc = j*8 + oc0;
            Ct[ oc   *CT_STRIDE + px_r    ] = acc[j][0];
            Ct[(oc+1)*CT_STRIDE + px_r    ] = acc[j][1];
            Ct[ oc   *CT_STRIDE + px_r + 8] = acc[j][2];
            Ct[(oc+1)*CT_STRIDE + px_r + 8] = acc[j][3];
        }
    }
    __syncthreads();
#pragma unroll
    for (int i = 0; i < 32; i++) {
        int idx = t + i*256;
        int oc = idx >> 7, px = idx & 127;
        g_conv[(size_t)(b*COUT + oc)*HW + P0 + px] = Ct[oc*CT_STRIDE + px];
    }
}

// ---------------- K3: BN batch stats over g_conv ----------------------------
__global__ __launch_bounds__(256) void k3_stats()
{
    const int slice = blockIdx.x, o = blockIdx.y, b = blockIdx.z;
    const float* p = g_conv + (size_t)(b*COUT + o)*HW + slice*4096;
    float s = 0.f, q = 0.f;
    for (int i = threadIdx.x; i < 4096; i += 256) {
        float v = p[i];
        s += v; q = fmaf(v, v, q);
    }
#pragma unroll
    for (int d = 16; d; d >>= 1) {
        s += __shfl_down_sync(0xFFFFFFFFu, s, d);
        q += __shfl_down_sync(0xFFFFFFFFu, q, d);
    }
    __shared__ float ss[8], qq[8];
    if ((threadIdx.x & 31) == 0) { ss[threadIdx.x >> 5] = s; qq[threadIdx.x >> 5] = q; }
    __syncthreads();
    if (threadIdx.x == 0) {
        float S = 0.f, Q = 0.f;
#pragma unroll
        for (int i = 0; i < 8; i++) { S += ss[i]; Q += qq[i]; }
        atomicAdd(&g_sum[o], S);
        atomicAdd(&g_sqsum[o], Q);
    }
}

// ---------------- K4: BatchNorm (batch stats) + ReLU + MaxPool2 -------------
__global__ void k4_bnpool(const float* __restrict__ gamma,
                          const float* __restrict__ beta,
                          float* __restrict__ out)
{
    int idx = blockIdx.x * blockDim.x + threadIdx.x;
    const int TOT = BATCH*COUT*96*96;
    if (idx >= TOT) return;
    int wo = idx % 96;
    int ho = (idx / 96) % 96;
    int o  = (idx / (96*96)) % COUT;
    int b  = idx / (96*96*COUT);

    const float inv = 1.f / (float)(BATCH*HH*WW);
    float mean = g_sum[o] * inv;
    float var  = g_sqsum[o] * inv - mean*mean;
    float sc = gamma[o] * rsqrtf(var + 1e-5f);
    float sh = beta[o] - mean * sc;

    const float* src = g_conv + ((size_t)(b*COUT + o)*HH + 2*ho)*WW + 2*wo;
    float a0 = fmaf(sc, src[0],    sh);
    float a1 = fmaf(sc, src[1],    sh);
    float a2 = fmaf(sc, src[WW],   sh);
    float a3 = fmaf(sc, src[WW+1], sh);
    float m = fmaxf(fmaxf(a0, a1), fmaxf(a2, a3));
    out[idx] = fmaxf(m, 0.f);
}

// ---------------- launch -----------------------------------------------------
extern "C" void kernel_launch(void* const* d_in, const int* in_sizes, int n_in,
                              void* d_out, int out_size)
{
    const float* x     = (const float*)d_in[0];
    const float* w_p   = (const float*)d_in[1];
    const float* b_p   = (const float*)d_in[2];
    const float* w_m   = (const float*)d_in[3];
    const float* b_m   = (const float*)d_in[4];
    const float* wconv = (const float*)d_in[5];
    const float* gamma = (const float*)d_in[6];
    const float* beta  = (const float*)d_in[7];
    float* out = (float*)d_out;

    cudaFuncSetAttribute(k2_main, cudaFuncAttributeMaxDynamicSharedMemorySize, 65536);

    k0_zero<<<1, 64>>>();
    k1_offmask<<<dim3(HH, BATCH), 192>>>(x, w_p, b_p, w_m, b_m);
    k2_main<<<dim3(HW/PXT, BATCH), 256, K2_SMEM_BYTES>>>(x, wconv);
    k3_stats<<<dim3(9, COUT, BATCH), 256>>>();
    int tot = BATCH*COUT*96*96;
    k4_bnpool<<<(tot + 255)/256, 256>>>(gamma, beta, out);
}

// round 12
// speedup vs baseline: 2.2245x; 1.6321x over previous
#include <cuda_runtime.h>
#include <math.h>
#include <stdint.h>

#define BATCH 4
#define CIN   64
#define COUT  64
#define HH    192
#define WW    192
#define NTAP  9
#define KTOT  576          // CIN * NTAP
#define HW    (HH*WW)
#define PXT   128          // pixels per block
#define KC    32           // K-chunk
#define NCHUNK (KTOT/KC)   // 18

// k2 smem word layout
#define AS_STRIDE 132      // As[32][132] k-major
#define BS_STRIDE 36       // Bs[64][36]  oc-major
#define CT_STRIDE 130      // Ct[64][130] epilogue transpose (reuses table area)
#define AS_WORDS  (KC*AS_STRIDE)            // 4224
#define BS_WORDS  (COUT*BS_STRIDE)          // 2304
#define TB_WORDS  (PXT*NTAP*8)              // 9216 (id4 + wg4)
#define K2_SMEM_BYTES ((AS_WORDS + BS_WORDS + TB_WORDS) * 4)   // 62976

// ---------------- scratch (device globals; no allocations allowed) ----------
__device__ float g_off [BATCH*18*HW];
__device__ float g_mask[BATCH*NTAP*HW];
__device__ float g_conv[BATCH*COUT*HW];
__device__ float g_sum  [COUT];
__device__ float g_sqsum[COUT];

__device__ __forceinline__ uint32_t f2tf32(float v) {
    uint32_t u;
    asm("cvt.rna.tf32.f32 %0, %1;" : "=r"(u) : "f"(v));
    return u;
}

__device__ __forceinline__ void mma_tf32(float* d, uint32_t a0, uint32_t a1,
                                         uint32_t a2, uint32_t a3,
                                         uint32_t b0, uint32_t b1) {
    asm volatile(
        "mma.sync.aligned.m16n8k8.row.col.f32.tf32.tf32.f32 "
        "{%0,%1,%2,%3}, {%4,%5,%6,%7}, {%8,%9}, {%0,%1,%2,%3};"
        : "+f"(d[0]), "+f"(d[1]), "+f"(d[2]), "+f"(d[3])
        : "r"(a0), "r"(a1), "r"(a2), "r"(a3), "r"(b0), "r"(b1));
}

// ---------------- K0: zero the BN stats -------------------------------------
__global__ void k0_zero() {
    int t = threadIdx.x;
    if (t < COUT) { g_sum[t] = 0.f; g_sqsum[t] = 0.f; }
}

// ---------------- K1: offset(18)+mask(9) 3x3 conv as TF32 tensor GEMM -------
// out[27][px] = W[27][k] * patch[k][px], k = c*9 + n, patch = shifted x.
// Block = 128 flat px, 256 threads (8 warps). Warp owns 16 px x 32 oc.
#define K1_BS_STRIDE 36
#define K1_SMEM_WORDS (AS_WORDS + 32*K1_BS_STRIDE)   // 4224 + 1152 = 5376

__global__ __launch_bounds__(256) void k1t_offmask(
    const float* __restrict__ x,
    const float* __restrict__ w_p, const float* __restrict__ b_p,
    const float* __restrict__ w_m, const float* __restrict__ b_m)
{
    __shared__ float smem[K1_SMEM_WORDS];
    float*    As  = smem;                 // [32][132]
    float*    Bs  = smem + AS_WORDS;      // [32][36]
    uint32_t* Asu = (uint32_t*)As;
    uint32_t* Bsu = (uint32_t*)Bs;

    const int t = threadIdx.x;
    const int wid = t >> 5, lane = t & 31;
    const int fg = lane >> 2, fi = lane & 3;
    const int P0 = blockIdx.x * PXT;
    const int b  = blockIdx.y;
    const int pxl = t & 127;
    const int P  = P0 + pxl;
    const int h  = P / WW, w = P - h*WW;

    float acc[4][4];
#pragma unroll
    for (int j = 0; j < 4; j++)
#pragma unroll
        for (int r = 0; r < 4; r++) acc[j][r] = 0.f;

    for (int chunk = 0; chunk < NCHUNK; ++chunk) {
        const int k0 = chunk * KC;
        // B tile: 32 oc x 32 k (rows 27..31 zero)
#pragma unroll
        for (int i = 0; i < 4; i++) {
            int e = t + i*256;
            int o = e >> 5, kl = e & 31;
            int k = k0 + kl;
            float v = 0.f;
            if (o < 18)      v = w_p[o*KTOT + k];
            else if (o < 27) v = w_m[(o-18)*KTOT + k];
            Bsu[o*K1_BS_STRIDE + kl] = f2tf32(v);
        }
        // A tile: 128 px x 32 k from shifted input (zero padded)
#pragma unroll
        for (int i = 0; i < 16; i++) {
            int kl = (t >> 7) + 2*i;
            int k = k0 + kl;
            int c = k / 9, n = k - 9*c;
            int gr = h + n/3 - 1, gc = w + (n % 3) - 1;
            float v = 0.f;
            if (gr >= 0 && gr < HH && gc >= 0 && gc < WW)
                v = x[((b*CIN + c)*HH + gr)*WW + gc];
            Asu[kl*AS_STRIDE + pxl] = f2tf32(v);
        }
        __syncthreads();

        const int px0 = wid * 16;
#pragma unroll
        for (int s = 0; s < 4; s++) {
            const uint32_t* Ab = Asu + (s*8 + fi)*AS_STRIDE + px0 + fg;
            uint32_t a0 = Ab[0];
            uint32_t a1 = Ab[8];
            uint32_t a2 = Ab[4*AS_STRIDE];
            uint32_t a3 = Ab[4*AS_STRIDE + 8];
#pragma unroll
            for (int j = 0; j < 4; j++) {
                const uint32_t* Bb = Bsu + (j*8 + fg)*K1_BS_STRIDE + s*8 + fi;
                mma_tf32(acc[j], a0, a1, a2, a3, Bb[0], Bb[4]);
            }
        }
        __syncthreads();
    }

    // epilogue: transpose through smem (reuse As), bias/sigmoid at store
    float* Ct = As;   // 32 rows x 130 = 4160 <= 4224 words
    {
        const int px_r = wid*16 + fg;
        const int oc0  = fi*2;
#pragma unroll
        for (int j = 0; j < 4; j++) {
            int oc = j*8 + oc0;
            Ct[ oc   *CT_STRIDE + px_r    ] = acc[j][0];
            Ct[(oc+1)*CT_STRIDE + px_r    ] = acc[j][1];
            Ct[ oc   *CT_STRIDE + px_r + 8] = acc[j][2];
            Ct[(oc+1)*CT_STRIDE + px_r + 8] = acc[j][3];
        }
    }
    __syncthreads();
#pragma unroll
    for (int ii = 0; ii < 14; ii++) {
        int idx = t + ii*256;
        if (idx >= 27*128) break;
        int oc = idx >> 7, px = idx & 127;
        float v = Ct[oc*CT_STRIDE + px];
        if (oc < 18) {
            g_off[(size_t)(b*18 + oc)*HW + P0 + px] = v + b_p[oc];
        } else {
            int mc = oc - 18;
            g_mask[(size_t)(b*NTAP + mc)*HW + P0 + px] =
                1.f/(1.f + expf(-(v + b_m[mc])));
        }
    }
}

// ---------------- K2: deformable sample + mma.sync TF32 GEMM + BN stats -----
__global__ __launch_bounds__(256) void k2_main(
    const float* __restrict__ x, const float* __restrict__ wconv)
{
    extern __shared__ float smem[];
    float*    As  = smem;                       // [32][132]
    float*    Bs  = smem + AS_WORDS;            // [64][36]; reused as stats
    float*    Tb  = smem + AS_WORDS + BS_WORDS; // tables, later Ct
    int4*     id4 = (int4*)Tb;                  // 1152 int4
    float4*   wg4 = (float4*)(Tb + 4608);       // 1152 float4
    uint32_t* Asu = (uint32_t*)As;
    uint32_t* Bsu = (uint32_t*)Bs;

    const int t = threadIdx.x;
    const int wid = t >> 5, lane = t & 31;
    const int fg = lane >> 2, fi = lane & 3;
    const int P0 = blockIdx.x * PXT;
    const int b  = blockIdx.y;

    // ---- gather tables: 128 px x 9 taps, stored [n][px]
    for (int it = t; it < PXT*NTAP; it += 256) {
        int n = it >> 7, px = it & 127;
        int P = P0 + px;
        int h = P / WW, w = P - h*WW;

        float offy = g_off [((b*18   + n    )*HH + h)*WW + w];
        float offx = g_off [((b*18   + 9 + n)*HH + h)*WW + w];
        float m    = g_mask[((b*NTAP + n    )*HH + h)*WW + w];

        float py  = (float)(h + 1) + (float)(n/3 - 1) + offy;   // padded coords
        float px_ = (float)(w + 1) + (float)(n%3 - 1) + offx;
        float fy = floorf(py), fx = floorf(px_);
        float qy0 = fminf(fmaxf(fy,       0.f), 193.f);
        float qy1 = fminf(fmaxf(fy + 1.f, 0.f), 193.f);
        float qx0 = fminf(fmaxf(fx,       0.f), 193.f);
        float qx1 = fminf(fmaxf(fx + 1.f, 0.f), 193.f);
        float pyc = fminf(fmaxf(py,  0.f), 193.f);
        float pxc = fminf(fmaxf(px_, 0.f), 193.f);
        float gy0 = 1.f + (qy0 - pyc);
        float gy1 = 1.f - (qy1 - pyc);
        float gx0 = 1.f + (qx0 - pxc);
        float gx1 = 1.f - (qx1 - pxc);
        int iy0 = (int)qy0, iy1 = (int)qy1, ix0 = (int)qx0, ix1 = (int)qx1;

        int4 id; float4 wg;
        bool inb = (iy0 >= 1) & (iy0 <= 192) & (ix0 >= 1) & (ix0 <= 192);
        id.x = inb ? (iy0-1)*WW + (ix0-1) : 0;  wg.x = inb ? gy0*gx0*m : 0.f;
        inb = (iy1 >= 1) & (iy1 <= 192) & (ix1 >= 1) & (ix1 <= 192);
        id.y = inb ? (iy1-1)*WW + (ix1-1) : 0;  wg.y = inb ? gy1*gx1*m : 0.f;
        inb = (iy0 >= 1) & (iy0 <= 192) & (ix1 >= 1) & (ix1 <= 192);
        id.z = inb ? (iy0-1)*WW + (ix1-1) : 0;  wg.z = inb ? gy0*gx1*m : 0.f;
        inb = (iy1 >= 1) & (iy1 <= 192) & (ix0 >= 1) & (ix0 <= 192);
        id.w = inb ? (iy1-1)*WW + (ix0-1) : 0;  wg.w = inb ? gy1*gx0*m : 0.f;

        id4[it] = id; wg4[it] = wg;
    }
    __syncthreads();

    float acc[8][4];
#pragma unroll
    for (int j = 0; j < 8; j++)
#pragma unroll
        for (int r = 0; r < 4; r++) acc[j][r] = 0.f;

    for (int chunk = 0; chunk < NCHUNK; ++chunk) {
        const int k0 = chunk * KC;

        // stage B: 64 oc x 32 k (coalesced gmem reads; Bs[oc][kl])
#pragma unroll
        for (int i = 0; i < 8; i++) {
            int e = t + i*256;
            int o = e >> 5, kl = e & 31;
            Bsu[o*BS_STRIDE + kl] = f2tf32(wconv[o*KTOT + k0 + kl]);
        }
        // sample A: 128 px x 32 k, stored k-major As[kl][px]
#pragma unroll
        for (int i = 0; i < 16; i++) {
            int e = t + i*256;
            int px = e & 127, kl = e >> 7;
            int k = k0 + kl;
            int c = k / 9, n = k - c*9;
            int4   id = id4[n*128 + px];
            float4 wg = wg4[n*128 + px];
            const float* base = x + (size_t)(b*CIN + c)*HW;
            float v = wg.x*base[id.x] + wg.y*base[id.y]
                    + wg.z*base[id.z] + wg.w*base[id.w];
            Asu[kl*AS_STRIDE + px] = f2tf32(v);
        }
        __syncthreads();

        const int px0 = wid * 16;
#pragma unroll
        for (int s = 0; s < 4; s++) {
            const uint32_t* Ab = Asu + (s*8 + fi)*AS_STRIDE + px0 + fg;
            uint32_t a0 = Ab[0];
            uint32_t a1 = Ab[8];
            uint32_t a2 = Ab[4*AS_STRIDE];
            uint32_t a3 = Ab[4*AS_STRIDE + 8];
#pragma unroll
            for (int j = 0; j < 8; j++) {
                const uint32_t* Bb = Bsu + (j*8 + fg)*BS_STRIDE + s*8 + fi;
                mma_tf32(acc[j], a0, a1, a2, a3, Bb[0], Bb[4]);
            }
        }
        __syncthreads();
    }

    // ---- epilogue: BN partial stats (smem, reusing Bs) + smem transpose ----
    float* ssum = Bs;        // 64
    float* ssq  = Bs + 64;   // 64
    if (t < 64) { ssum[t] = 0.f; ssq[t] = 0.f; }

    float* Ct = Tb;          // [64][130]
    {
        const int px_r = wid*16 + fg;
        const int oc0  = fi*2;
#pragma unroll
        for (int j = 0; j < 8; j++) {
            int oc = j*8 + oc0;
            Ct[ oc   *CT_STRIDE + px_r    ] = acc[j][0];
            Ct[(oc+1)*CT_STRIDE + px_r    ] = acc[j][1];
            Ct[ oc   *CT_STRIDE + px_r + 8] = acc[j][2];
            Ct[(oc+1)*CT_STRIDE + px_r + 8] = acc[j][3];
        }
    }
    __syncthreads();

    // per-oc partial sums from registers
    {
        const int oc0 = fi*2;
#pragma unroll
        for (int j = 0; j < 8; j++) {
            int oc = j*8 + oc0;
            atomicAdd(&ssum[oc],   acc[j][0] + acc[j][2]);
            atomicAdd(&ssum[oc+1], acc[j][1] + acc[j][3]);
            atomicAdd(&ssq[oc],   fmaf(acc[j][0],acc[j][0], acc[j][2]*acc[j][2]));
            atomicAdd(&ssq[oc+1], fmaf(acc[j][1],acc[j][1], acc[j][3]*acc[j][3]));
        }
    }
    // coalesced stores of the conv output
#pragma unroll
    for (int i = 0; i < 32; i++) {
        int idx = t + i*256;
        int oc = idx >> 7, px = idx & 127;
        g_conv[(size_t)(b*COUT + oc)*HW + P0 + px] = Ct[oc*CT_STRIDE + px];
    }
    __syncthreads();
    if (t < 64) {
        atomicAdd(&g_sum[t],   ssum[t]);
        atomicAdd(&g_sqsum[t], ssq[t]);
    }
}

// ---------------- K4: BatchNorm (batch stats) + ReLU + MaxPool2 -------------
__global__ void k4_bnpool(const float* __restrict__ gamma,
                          const float* __restrict__ beta,
                          float* __restrict__ out)
{
    int idx = blockIdx.x * blockDim.x + threadIdx.x;
    const int TOT = BATCH*COUT*96*96;
    if (idx >= TOT) return;
    int wo = idx % 96;
    int ho = (idx / 96) % 96;
    int o  = (idx / (96*96)) % COUT;
    int b  = idx / (96*96*COUT);

    const float inv = 1.f / (float)(BATCH*HH*WW);
    float mean = g_sum[o] * inv;
    float var  = g_sqsum[o] * inv - mean*mean;
    float sc = gamma[o] * rsqrtf(var + 1e-5f);
    float sh = beta[o] - mean * sc;

    const float* src = g_conv + ((size_t)(b*COUT + o)*HH + 2*ho)*WW + 2*wo;
    float a0 = fmaf(sc, src[0],    sh);
    float a1 = fmaf(sc, src[1],    sh);
    float a2 = fmaf(sc, src[WW],   sh);
    float a3 = fmaf(sc, src[WW+1], sh);
    float m = fmaxf(fmaxf(a0, a1), fmaxf(a2, a3));
    out[idx] = fmaxf(m, 0.f);
}

// ---------------- launch -----------------------------------------------------
extern "C" void kernel_launch(void* const* d_in, const int* in_sizes, int n_in,
                              void* d_out, int out_size)
{
    const float* x     = (const float*)d_in[0];
    const float* w_p   = (const float*)d_in[1];
    const float* b_p   = (const float*)d_in[2];
    const float* w_m   = (const float*)d_in[3];
    const float* b_m   = (const float*)d_in[4];
    const float* wconv = (const float*)d_in[5];
    const float* gamma = (const float*)d_in[6];
    const float* beta  = (const float*)d_in[7];
    float* out = (float*)d_out;

    cudaFuncSetAttribute(k2_main, cudaFuncAttributeMaxDynamicSharedMemorySize, 65536);

    k0_zero<<<1, 64>>>();
    k1t_offmask<<<dim3(HW/PXT, BATCH), 256>>>(x, w_p, b_p, w_m, b_m);
    k2_main<<<dim3(HW/PXT, BATCH), 256, K2_SMEM_BYTES>>>(x, wconv);
    int tot = BATCH*COUT*96*96;
    k4_bnpool<<<(tot + 255)/256, 256>>>(gamma, beta, out);
}